// round 9
// baseline (speedup 1.0000x reference)
#include <cuda_runtime.h>
#include <cstdint>
#include <math.h>

#define DIMV 32
#define KN 16
#define NREL 60
#define MAXB 8192
#define NTASK 17
#define WPB 8

// scratch (device globals)
__device__ float g_uemb [MAXB * DIMV];
__device__ int   g_e1id [MAXB * KN];
__device__ float g_attn0[MAXB * KN];
__device__ int   g_e2id [MAXB * KN * KN];
__device__ float g_attn1[MAXB * KN * KN];
__device__ float g_t    [MAXB * NTASK * DIMV];

__device__ __forceinline__ float sigm(float x) { return 1.f / (1.f + __expf(-x)); }

__device__ __forceinline__ float softmax16(float sc) {
    float m = sc;
    #pragma unroll
    for (int o = 8; o > 0; o >>= 1) m = fmaxf(m, __shfl_xor_sync(0xffffffffu, m, o, 16));
    float e = __expf(sc - m);
    float s = e;
    #pragma unroll
    for (int o = 8; o > 0; o >>= 1) s += __shfl_xor_sync(0xffffffffu, s, o, 16);
    return e / s;
}

__device__ __forceinline__ float udr_lookup(float u0, float u1, int rid) {
    float a = __shfl_sync(0xffffffffu, u0, rid & 31);
    float b = __shfl_sync(0xffffffffu, u1, rid & 31);
    return (rid < 32) ? a : b;
}

__device__ __forceinline__ unsigned int smem_u32(const void* p) {
    return (unsigned int)__cvta_generic_to_shared(p);
}
__device__ __forceinline__ void cp4(unsigned int dst, const float* src) {
    asm volatile("cp.async.ca.shared.global [%0], [%1], 4;" :: "r"(dst), "l"(src));
}
__device__ __forceinline__ void cp_wait_all() {
    asm volatile("cp.async.commit_group;\ncp.async.wait_group 0;" ::: "memory");
}

// ---- KA: warp per element. ids, uemb, udotr, attention weights. ----------
__global__ __launch_bounds__(256, 6) void ka_kernel(
    const int*   __restrict__ users,
    const int*   __restrict__ items,
    const float* __restrict__ emb,
    const float* __restrict__ rel,
    const int*   __restrict__ adjE,
    const int*   __restrict__ adjR,
    const int*   __restrict__ hist,
    int B)
{
    __shared__ float rels[NREL * DIMV];   // swizzled [r*32 + ((d+r)&31)]

    const int tid = threadIdx.x, lane = tid & 31, w = tid >> 5;
    #pragma unroll
    for (int i = tid; i < NREL * DIMV; i += 256) {
        int r = i >> 5, d = i & 31;
        rels[r * DIMV + ((d + r) & 31)] = __ldg(&rel[i]);
    }
    __syncthreads();

    const int b = blockIdx.x * 8 + w;
    if (b >= B) return;

    const int uid  = __ldg(&users[b]);
    const int item = __ldg(&items[b]);
    const int kl   = lane & 15;

    const int hid = __ldg(&hist[(size_t)uid  * KN + kl]);
    const int e1  = __ldg(&adjE[(size_t)item * KN + kl]);
    const int r0  = __ldg(&adjR[(size_t)item * KN + kl]);

    // user embedding: batch the 16 independent row loads
    float hv[8];
    float us = 0.f;
    #pragma unroll
    for (int h = 0; h < 2; ++h) {
        #pragma unroll
        for (int k = 0; k < 8; ++k) {
            int id = __shfl_sync(0xffffffffu, hid, h * 8 + k);
            hv[k] = __ldg(&emb[(size_t)id * DIMV + lane]);
        }
        #pragma unroll
        for (int k = 0; k < 8; ++k) us += hv[k];
    }
    const float uemb = us * (1.f / 16.f);
    g_uemb[b * DIMV + lane] = uemb;

    // udotr: lane r holds udotr[r] (u0) and udotr[r+32] (u1)
    float u0 = 0.f, u1 = 0.f;
    const int r2 = lane + 32;
    #pragma unroll
    for (int d = 0; d < DIMV; ++d) {
        float ud = __shfl_sync(0xffffffffu, uemb, d);
        u0 += ud * rels[lane * DIMV + ((d + lane) & 31)];
        if (r2 < NREL) u1 += ud * rels[r2 * DIMV + ((d + r2) & 31)];
    }

    // hop-0 attention + e1 ids
    float a0 = softmax16(udr_lookup(u0, u1, r0));
    if (lane < KN) {
        g_e1id [b * KN + lane] = e1;
        g_attn0[b * KN + lane] = a0;
    }

    // hop-2 adjacency + hop-1 attention: 8 iters x (2 rows x 16 cols)
    #pragma unroll
    for (int p = 0; p < 8; ++p) {
        int row  = 2 * p + (lane >> 4);
        int base = __shfl_sync(0xffffffffu, e1, row);
        int id   = __ldg(&adjE[(size_t)base * KN + kl]);
        int rid  = __ldg(&adjR[(size_t)base * KN + kl]);
        float a  = softmax16(udr_lookup(u0, u1, rid));
        size_t o = (size_t)b * 256 + row * KN + kl;
        g_e2id [o] = id;
        g_attn1[o] = a;
    }
}

// ---- KB: warp per (element, task). cp.async 16-deep gather + matvec. -----
__global__ __launch_bounds__(256, 6) void kb_kernel(
    const int*   __restrict__ items,
    const float* __restrict__ emb,
    const float* __restrict__ W,
    const float* __restrict__ bvec,
    int B)
{
    __shared__ float Ws[DIMV * DIMV];
    __shared__ float bs[DIMV];
    __shared__ float stage[WPB][KN][DIMV];

    const int tid = threadIdx.x, lane = tid & 31, w = tid >> 5;
    #pragma unroll
    for (int i = tid; i < DIMV * DIMV; i += 256) Ws[i] = __ldg(&W[i]);
    if (tid < DIMV) bs[tid] = __ldg(&bvec[tid]);
    __syncthreads();

    const int task = blockIdx.x * WPB + w;
    const int b = task / NTASK;
    const int t = task - b * NTASK;
    if (b >= B) return;

    // id / weight / self-row sources (uniform work after this)
    int   id  = 0;
    float wgt = 0.f;
    int   selfid;
    if (t < KN) {
        if (lane < KN) {
            size_t o = (size_t)b * 256 + t * KN + lane;
            id  = __ldg(&g_e2id [o]);
            wgt = __ldg(&g_attn1[o]);
        }
        selfid = __ldg(&g_e1id[b * KN + t]);
    } else {
        if (lane < KN) {
            id  = __ldg(&g_e1id [b * KN + lane]);
            wgt = __ldg(&g_attn0[b * KN + lane]);
        }
        selfid = __ldg(&items[b]);
    }

    // 16-deep async gather into per-warp stage (no register pressure)
    const unsigned int sbase = smem_u32(&stage[w][0][lane]);
    #pragma unroll
    for (int k = 0; k < KN; ++k) {
        int ik = __shfl_sync(0xffffffffu, id, k);
        cp4(sbase + k * (DIMV * 4), emb + (size_t)ik * DIMV + lane);
    }
    float x = __ldg(&emb[(size_t)selfid * DIMV + lane]);   // overlaps with cp.async
    cp_wait_all();
    __syncwarp();

    #pragma unroll
    for (int k = 0; k < KN; ++k)
        x += __shfl_sync(0xffffffffu, wgt, k) * stage[w][k][lane];

    float y = bs[lane];
    #pragma unroll
    for (int j = 0; j < DIMV; ++j)
        y += __shfl_sync(0xffffffffu, x, j) * Ws[j * DIMV + lane];

    g_t[((size_t)b * NTASK + t) * DIMV + lane] = sigm(y);
}

// ---- KC: warp per element. Final matvec + score. -------------------------
__global__ __launch_bounds__(256, 8) void kc_kernel(
    const float* __restrict__ W,
    const float* __restrict__ bvec,
    float*       __restrict__ out,
    int B)
{
    __shared__ float Ws[DIMV * DIMV];
    __shared__ float bs[DIMV];
    const int tid = threadIdx.x, lane = tid & 31, w = tid >> 5;
    #pragma unroll
    for (int i = tid; i < DIMV * DIMV; i += 256) Ws[i] = __ldg(&W[i]);
    if (tid < DIMV) bs[tid] = __ldg(&bvec[tid]);
    __syncthreads();

    const int b = blockIdx.x * 8 + w;
    if (b >= B) return;

    float a0 = (lane < KN) ? __ldg(&g_attn0[b * KN + lane]) : 0.f;
    const float* tb = g_t + (size_t)b * NTASK * DIMV;

    float t0 = __ldg(&tb[16 * DIMV + lane]);
    float accf = 0.f;
    #pragma unroll
    for (int k = 0; k < KN; ++k) {
        float ak = __shfl_sync(0xffffffffu, a0, k);
        accf += ak * __ldg(&tb[k * DIMV + lane]);
    }
    float xf = t0 + accf;
    float yf = bs[lane];
    #pragma unroll
    for (int j = 0; j < DIMV; ++j)
        yf += __shfl_sync(0xffffffffu, xf, j) * Ws[j * DIMV + lane];
    float f = tanhf(yf);

    float s = __ldg(&g_uemb[b * DIMV + lane]) * f;
    #pragma unroll
    for (int o = 16; o > 0; o >>= 1) s += __shfl_xor_sync(0xffffffffu, s, o);
    if (lane == 0) out[b] = sigm(s);
}

extern "C" void kernel_launch(void* const* d_in, const int* in_sizes, int n_in,
                              void* d_out, int out_size) {
    const int*   users        = (const int*)  d_in[0];
    const int*   items        = (const int*)  d_in[1];
    const float* entity_emb   = (const float*)d_in[2];
    const float* relation_emb = (const float*)d_in[3];
    const int*   adj_entity   = (const int*)  d_in[4];
    const int*   adj_relation = (const int*)  d_in[5];
    const int*   user_history = (const int*)  d_in[6];
    const float* W            = (const float*)d_in[7];
    const float* b            = (const float*)d_in[8];
    float* out = (float*)d_out;

    int B = in_sizes[0];
    ka_kernel<<<(B + 7) / 8, 256>>>(users, items, entity_emb, relation_emb,
                                    adj_entity, adj_relation, user_history, B);
    kb_kernel<<<(B * NTASK + WPB - 1) / WPB, 256>>>(items, entity_emb, W, b, B);
    kc_kernel<<<(B + 7) / 8, 256>>>(W, b, out, B);
}

// round 10
// speedup vs baseline: 1.1994x; 1.1994x over previous
#include <cuda_runtime.h>
#include <cstdint>
#include <math.h>

#define DIMV 32
#define KN 16
#define NREL 60
#define MAXB 8192
#define NTASK 17
#define WPB 8

// scratch (device globals)
__device__ float g_uemb [MAXB * DIMV];
__device__ int   g_e1id [MAXB * KN];
__device__ float g_attn0[MAXB * KN];
__device__ int   g_e2id [MAXB * KN * KN];
__device__ float g_attn1[MAXB * KN * KN];
__device__ float g_t    [MAXB * NTASK * DIMV];

__device__ __forceinline__ float sigm(float x) { return 1.f / (1.f + __expf(-x)); }

__device__ __forceinline__ float softmax16(float sc) {
    float m = sc;
    #pragma unroll
    for (int o = 8; o > 0; o >>= 1) m = fmaxf(m, __shfl_xor_sync(0xffffffffu, m, o, 16));
    float e = __expf(sc - m);
    float s = e;
    #pragma unroll
    for (int o = 8; o > 0; o >>= 1) s += __shfl_xor_sync(0xffffffffu, s, o, 16);
    return e / s;
}

__device__ __forceinline__ float udr_lookup(float u0, float u1, int rid) {
    float a = __shfl_sync(0xffffffffu, u0, rid & 31);
    float b = __shfl_sync(0xffffffffu, u1, rid & 31);
    return (rid < 32) ? a : b;
}

// ---- KA: warp per element. ids, uemb, udotr, attention weights. ----------
__global__ __launch_bounds__(256, 6) void ka_kernel(
    const int*   __restrict__ users,
    const int*   __restrict__ items,
    const float* __restrict__ emb,
    const float* __restrict__ rel,
    const int*   __restrict__ adjE,
    const int*   __restrict__ adjR,
    const int*   __restrict__ hist,
    int B)
{
    __shared__ float rels[NREL * DIMV];   // swizzled [r*32 + ((d+r)&31)]

    const int tid = threadIdx.x, lane = tid & 31, w = tid >> 5;
    #pragma unroll
    for (int i = tid; i < NREL * DIMV; i += 256) {
        int r = i >> 5, d = i & 31;
        rels[r * DIMV + ((d + r) & 31)] = __ldg(&rel[i]);
    }
    __syncthreads();

    const int b = blockIdx.x * 8 + w;
    if (b >= B) return;

    const int uid  = __ldg(&users[b]);
    const int item = __ldg(&items[b]);
    const int kl   = lane & 15;

    const int hid = __ldg(&hist[(size_t)uid  * KN + kl]);
    const int e1  = __ldg(&adjE[(size_t)item * KN + kl]);
    const int r0  = __ldg(&adjR[(size_t)item * KN + kl]);

    // user embedding: float4 gather, 4 rows per round, 2 rounds in flight
    const int c = lane & 7, g = lane >> 3;
    float4 hv[4];
    #pragma unroll
    for (int p = 0; p < 4; ++p) {
        int id = __shfl_sync(0xffffffffu, hid, p * 4 + g);
        hv[p] = __ldg((const float4*)(emb + (size_t)id * DIMV) + c);
    }
    float4 us4;
    us4.x = hv[0].x + hv[1].x + hv[2].x + hv[3].x;
    us4.y = hv[0].y + hv[1].y + hv[2].y + hv[3].y;
    us4.z = hv[0].z + hv[1].z + hv[2].z + hv[3].z;
    us4.w = hv[0].w + hv[1].w + hv[2].w + hv[3].w;
    #pragma unroll
    for (int o = 8; o <= 16; o <<= 1) {
        us4.x += __shfl_xor_sync(0xffffffffu, us4.x, o);
        us4.y += __shfl_xor_sync(0xffffffffu, us4.y, o);
        us4.z += __shfl_xor_sync(0xffffffffu, us4.z, o);
        us4.w += __shfl_xor_sync(0xffffffffu, us4.w, o);
    }
    // redistribute: lane holds uemb[lane]
    float uemb;
    {
        int src = lane >> 2;
        float ux = __shfl_sync(0xffffffffu, us4.x, src);
        float uy = __shfl_sync(0xffffffffu, us4.y, src);
        float uz = __shfl_sync(0xffffffffu, us4.z, src);
        float uw = __shfl_sync(0xffffffffu, us4.w, src);
        int m = lane & 3;
        uemb = (m == 0) ? ux : (m == 1) ? uy : (m == 2) ? uz : uw;
        uemb *= (1.f / 16.f);
    }
    g_uemb[b * DIMV + lane] = uemb;

    // udotr: lane r holds udotr[r] (u0) and udotr[r+32] (u1)
    float u0 = 0.f, u1 = 0.f;
    const int r2 = lane + 32;
    #pragma unroll
    for (int d = 0; d < DIMV; ++d) {
        float ud = __shfl_sync(0xffffffffu, uemb, d);
        u0 += ud * rels[lane * DIMV + ((d + lane) & 31)];
        if (r2 < NREL) u1 += ud * rels[r2 * DIMV + ((d + r2) & 31)];
    }

    // hop-0 attention + e1 ids
    float a0 = softmax16(udr_lookup(u0, u1, r0));
    if (lane < KN) {
        g_e1id [b * KN + lane] = e1;
        g_attn0[b * KN + lane] = a0;
    }

    // hop-2 adjacency + hop-1 attention: 8 iters x (2 rows x 16 cols)
    #pragma unroll
    for (int p = 0; p < 8; ++p) {
        int row  = 2 * p + (lane >> 4);
        int base = __shfl_sync(0xffffffffu, e1, row);
        int id   = __ldg(&adjE[(size_t)base * KN + kl]);
        int rid  = __ldg(&adjR[(size_t)base * KN + kl]);
        float a  = softmax16(udr_lookup(u0, u1, rid));
        size_t o = (size_t)b * 256 + row * KN + kl;
        g_e2id [o] = id;
        g_attn1[o] = a;
    }
}

// ---- KB: warp per (element, task). float4 gather, 4 LDG.128/thread. ------
__global__ __launch_bounds__(256, 6) void kb_kernel(
    const int*   __restrict__ items,
    const float* __restrict__ emb,
    const float* __restrict__ W,
    const float* __restrict__ bvec,
    int B)
{
    __shared__ float Ws[DIMV * DIMV];
    __shared__ float bs[DIMV];

    const int tid = threadIdx.x, lane = tid & 31, w = tid >> 5;
    #pragma unroll
    for (int i = tid; i < DIMV * DIMV; i += 256) Ws[i] = __ldg(&W[i]);
    if (tid < DIMV) bs[tid] = __ldg(&bvec[tid]);
    __syncthreads();

    const int task = blockIdx.x * WPB + w;
    const int b = task / NTASK;
    const int t = task - b * NTASK;
    if (b >= B) return;

    int   id  = 0;
    float wgt = 0.f;
    int   selfid;
    if (t < KN) {
        if (lane < KN) {
            size_t o = (size_t)b * 256 + t * KN + lane;
            id  = __ldg(&g_e2id [o]);
            wgt = __ldg(&g_attn1[o]);
        }
        selfid = __ldg(&g_e1id[b * KN + t]);
    } else {
        if (lane < KN) {
            id  = __ldg(&g_e1id [b * KN + lane]);
            wgt = __ldg(&g_attn0[b * KN + lane]);
        }
        selfid = __ldg(&items[b]);
    }

    // float4 gather: lane (g, c) loads row p*4+g, columns c*4..c*4+3
    const int c = lane & 7, g = lane >> 3;
    float4 v[4];
    #pragma unroll
    for (int p = 0; p < 4; ++p) {
        int ik = __shfl_sync(0xffffffffu, id, p * 4 + g);
        v[p] = __ldg((const float4*)(emb + (size_t)ik * DIMV) + c);
    }
    float4 sv = __ldg((const float4*)(emb + (size_t)selfid * DIMV) + c);

    float4 acc = make_float4(0.f, 0.f, 0.f, 0.f);
    #pragma unroll
    for (int p = 0; p < 4; ++p) {
        float wk = __shfl_sync(0xffffffffu, wgt, p * 4 + g);
        acc.x += wk * v[p].x; acc.y += wk * v[p].y;
        acc.z += wk * v[p].z; acc.w += wk * v[p].w;
    }
    #pragma unroll
    for (int o = 8; o <= 16; o <<= 1) {
        acc.x += __shfl_xor_sync(0xffffffffu, acc.x, o);
        acc.y += __shfl_xor_sync(0xffffffffu, acc.y, o);
        acc.z += __shfl_xor_sync(0xffffffffu, acc.z, o);
        acc.w += __shfl_xor_sync(0xffffffffu, acc.w, o);
    }
    float4 x4;
    x4.x = sv.x + acc.x; x4.y = sv.y + acc.y;
    x4.z = sv.z + acc.z; x4.w = sv.w + acc.w;

    // matvec: x columns live in lanes 0-7 (replicated across g); 8x4 shfl
    float y = bs[lane];
    #pragma unroll
    for (int jc = 0; jc < 8; ++jc) {
        float xx = __shfl_sync(0xffffffffu, x4.x, jc);
        float xy = __shfl_sync(0xffffffffu, x4.y, jc);
        float xz = __shfl_sync(0xffffffffu, x4.z, jc);
        float xw = __shfl_sync(0xffffffffu, x4.w, jc);
        y += xx * Ws[(jc * 4 + 0) * DIMV + lane];
        y += xy * Ws[(jc * 4 + 1) * DIMV + lane];
        y += xz * Ws[(jc * 4 + 2) * DIMV + lane];
        y += xw * Ws[(jc * 4 + 3) * DIMV + lane];
    }

    g_t[((size_t)b * NTASK + t) * DIMV + lane] = sigm(y);
}

// ---- KC: warp per element. Final matvec + score. -------------------------
__global__ __launch_bounds__(256, 8) void kc_kernel(
    const float* __restrict__ W,
    const float* __restrict__ bvec,
    float*       __restrict__ out,
    int B)
{
    __shared__ float Ws[DIMV * DIMV];
    __shared__ float bs[DIMV];
    const int tid = threadIdx.x, lane = tid & 31, w = tid >> 5;
    #pragma unroll
    for (int i = tid; i < DIMV * DIMV; i += 256) Ws[i] = __ldg(&W[i]);
    if (tid < DIMV) bs[tid] = __ldg(&bvec[tid]);
    __syncthreads();

    const int b = blockIdx.x * 8 + w;
    if (b >= B) return;

    float a0 = (lane < KN) ? __ldg(&g_attn0[b * KN + lane]) : 0.f;
    const float* tb = g_t + (size_t)b * NTASK * DIMV;

    float t0 = __ldg(&tb[16 * DIMV + lane]);
    float accf = 0.f;
    #pragma unroll
    for (int k = 0; k < KN; ++k) {
        float ak = __shfl_sync(0xffffffffu, a0, k);
        accf += ak * __ldg(&tb[k * DIMV + lane]);
    }
    float xf = t0 + accf;
    float yf = bs[lane];
    #pragma unroll
    for (int j = 0; j < DIMV; ++j)
        yf += __shfl_sync(0xffffffffu, xf, j) * Ws[j * DIMV + lane];
    float f = tanhf(yf);

    float s = __ldg(&g_uemb[b * DIMV + lane]) * f;
    #pragma unroll
    for (int o = 16; o > 0; o >>= 1) s += __shfl_xor_sync(0xffffffffu, s, o);
    if (lane == 0) out[b] = sigm(s);
}

extern "C" void kernel_launch(void* const* d_in, const int* in_sizes, int n_in,
                              void* d_out, int out_size) {
    const int*   users        = (const int*)  d_in[0];
    const int*   items        = (const int*)  d_in[1];
    const float* entity_emb   = (const float*)d_in[2];
    const float* relation_emb = (const float*)d_in[3];
    const int*   adj_entity   = (const int*)  d_in[4];
    const int*   adj_relation = (const int*)  d_in[5];
    const int*   user_history = (const int*)  d_in[6];
    const float* W            = (const float*)d_in[7];
    const float* b            = (const float*)d_in[8];
    float* out = (float*)d_out;

    int B = in_sizes[0];
    ka_kernel<<<(B + 7) / 8, 256>>>(users, items, entity_emb, relation_emb,
                                    adj_entity, adj_relation, user_history, B);
    kb_kernel<<<(B * NTASK + WPB - 1) / WPB, 256>>>(items, entity_emb, W, b, B);
    kc_kernel<<<(B + 7) / 8, 256>>>(W, b, out, B);
}

// round 11
// speedup vs baseline: 1.3045x; 1.0876x over previous
#include <cuda_runtime.h>
#include <math.h>

#define DIMV 32
#define KN 16
#define NREL 60
#define MAXB 8192

// scratch (device globals)
__device__ float g_uemb [MAXB * DIMV];
__device__ int   g_e1id [MAXB * KN];
__device__ float g_attn0[MAXB * KN];
__device__ int   g_e2id [MAXB * KN * KN];
__device__ float g_attn1[MAXB * KN * KN];
__device__ float g_t    [MAXB * KN * DIMV];

__device__ __forceinline__ float sigm(float x) { return 1.f / (1.f + __expf(-x)); }

__device__ __forceinline__ float softmax16(float sc) {
    float m = sc;
    #pragma unroll
    for (int o = 8; o > 0; o >>= 1) m = fmaxf(m, __shfl_xor_sync(0xffffffffu, m, o, 16));
    float e = __expf(sc - m);
    float s = e;
    #pragma unroll
    for (int o = 8; o > 0; o >>= 1) s += __shfl_xor_sync(0xffffffffu, s, o, 16);
    return e / s;
}

__device__ __forceinline__ float udr_lookup(float u0, float u1, int rid) {
    float a = __shfl_sync(0xffffffffu, u0, rid & 31);
    float b = __shfl_sync(0xffffffffu, u1, rid & 31);
    return (rid < 32) ? a : b;
}

// ---- KA: warp per element (exact R6 form, 20.6us). -----------------------
__global__ __launch_bounds__(256, 6) void ka_kernel(
    const int*   __restrict__ users,
    const int*   __restrict__ items,
    const float* __restrict__ emb,
    const float* __restrict__ rel,
    const int*   __restrict__ adjE,
    const int*   __restrict__ adjR,
    const int*   __restrict__ hist,
    int B)
{
    __shared__ float rels[NREL * DIMV];   // swizzled [r*32 + ((d+r)&31)]

    const int tid = threadIdx.x, lane = tid & 31, w = tid >> 5;
    #pragma unroll
    for (int i = tid; i < NREL * DIMV; i += 256) {
        int r = i >> 5, d = i & 31;
        rels[r * DIMV + ((d + r) & 31)] = __ldg(&rel[i]);
    }
    __syncthreads();

    const int b = blockIdx.x * 8 + w;
    if (b >= B) return;

    const int uid  = __ldg(&users[b]);
    const int item = __ldg(&items[b]);
    const int kl   = lane & 15;

    const int hid = __ldg(&hist[(size_t)uid  * KN + kl]);
    const int e1  = __ldg(&adjE[(size_t)item * KN + kl]);
    const int r0  = __ldg(&adjR[(size_t)item * KN + kl]);

    // user embedding: batch the 16 independent row loads
    float hv[8];
    float us = 0.f;
    #pragma unroll
    for (int h = 0; h < 2; ++h) {
        #pragma unroll
        for (int k = 0; k < 8; ++k) {
            int id = __shfl_sync(0xffffffffu, hid, h * 8 + k);
            hv[k] = __ldg(&emb[(size_t)id * DIMV + lane]);
        }
        #pragma unroll
        for (int k = 0; k < 8; ++k) us += hv[k];
    }
    const float uemb = us * (1.f / 16.f);
    g_uemb[b * DIMV + lane] = uemb;

    // udotr: lane r holds udotr[r] (u0) and udotr[r+32] (u1)
    float u0 = 0.f, u1 = 0.f;
    const int r2 = lane + 32;
    #pragma unroll
    for (int d = 0; d < DIMV; ++d) {
        float ud = __shfl_sync(0xffffffffu, uemb, d);
        u0 += ud * rels[lane * DIMV + ((d + lane) & 31)];
        if (r2 < NREL) u1 += ud * rels[r2 * DIMV + ((d + r2) & 31)];
    }

    // hop-0 attention + e1 ids
    float a0 = softmax16(udr_lookup(u0, u1, r0));
    if (lane < KN) {
        g_e1id [b * KN + lane] = e1;
        g_attn0[b * KN + lane] = a0;
    }

    // hop-2 adjacency + hop-1 attention: 8 iters x (2 rows x 16 cols)
    #pragma unroll
    for (int p = 0; p < 8; ++p) {
        int row  = 2 * p + (lane >> 4);
        int base = __shfl_sync(0xffffffffu, e1, row);
        int id   = __ldg(&adjE[(size_t)base * KN + kl]);
        int rid  = __ldg(&adjR[(size_t)base * KN + kl]);
        float a  = softmax16(udr_lookup(u0, u1, rid));
        size_t o = (size_t)b * 256 + row * KN + kl;
        g_e2id [o] = id;
        g_attn1[o] = a;
    }
}

// ---- KB: warp per quad of hop-1 nodes. Register W, zero smem. ------------
__global__ __launch_bounds__(256, 4) void kb_kernel(
    const float* __restrict__ emb,
    const float* __restrict__ W,
    const float* __restrict__ bvec,
    int B)
{
    const int tid = threadIdx.x, lane = tid & 31, w = tid >> 5;
    const int q = blockIdx.x * 8 + w;
    const int b = q >> 2, quad = q & 3;
    if (b >= B) return;

    float Wcol[DIMV];
    #pragma unroll
    for (int j = 0; j < DIMV; ++j) Wcol[j] = __ldg(&W[j * DIMV + lane]);
    const float bl = __ldg(&bvec[lane]);

    // 64 ids + 64 weights for this quad, 2 per lane (coalesced)
    const int2*   idp = (const int2*)  (g_e2id  + (size_t)b * 256 + quad * 64);
    const float2* wtp = (const float2*)(g_attn1 + (size_t)b * 256 + quad * 64);
    const int2   id2 = __ldg(&idp[lane]);
    const float2 wt2 = __ldg(&wtp[lane]);

    #pragma unroll
    for (int t = 0; t < 4; ++t) {
        const int n = quad * 4 + t;
        const int selfid = __ldg(&g_e1id[b * KN + n]);
        float x = __ldg(&emb[(size_t)selfid * DIMV + lane]);

        #pragma unroll
        for (int h = 0; h < 2; ++h) {
            float va[4], vb[4];
            #pragma unroll
            for (int p = 0; p < 4; ++p) {
                int src = t * 8 + h * 4 + p;     // pair (k=2src%16, 2src%16+1)
                int ia = __shfl_sync(0xffffffffu, id2.x, src);
                int ib = __shfl_sync(0xffffffffu, id2.y, src);
                va[p] = __ldg(&emb[(size_t)ia * DIMV + lane]);
                vb[p] = __ldg(&emb[(size_t)ib * DIMV + lane]);
            }
            #pragma unroll
            for (int p = 0; p < 4; ++p) {
                int src = t * 8 + h * 4 + p;
                x += __shfl_sync(0xffffffffu, wt2.x, src) * va[p];
                x += __shfl_sync(0xffffffffu, wt2.y, src) * vb[p];
            }
        }

        float y = bl;
        #pragma unroll
        for (int j = 0; j < DIMV; ++j)
            y += __shfl_sync(0xffffffffu, x, j) * Wcol[j];

        g_t[((size_t)b * KN + n) * DIMV + lane] = sigm(y);
    }
}

// ---- KC: warp per element. hop-0 node + final matvec + score. ------------
__global__ __launch_bounds__(256, 4) void kc_kernel(
    const int*   __restrict__ items,
    const float* __restrict__ emb,
    const float* __restrict__ W,
    const float* __restrict__ bvec,
    float*       __restrict__ out,
    int B)
{
    const int tid = threadIdx.x, lane = tid & 31, w = tid >> 5;
    const int b = blockIdx.x * 8 + w;
    if (b >= B) return;

    float Wcol[DIMV];
    #pragma unroll
    for (int j = 0; j < DIMV; ++j) Wcol[j] = __ldg(&W[j * DIMV + lane]);
    const float bl = __ldg(&bvec[lane]);

    const float a0 = (lane < KN) ? __ldg(&g_attn0[b * KN + lane]) : 0.f;
    const int   e1 = (lane < KN) ? __ldg(&g_e1id [b * KN + lane]) : 0;
    const int item = __ldg(&items[b]);

    // hop-0 node: item row + 16 e1-row gather
    float x0 = __ldg(&emb[(size_t)item * DIMV + lane]);
    #pragma unroll
    for (int h = 0; h < 2; ++h) {
        float v[8];
        #pragma unroll
        for (int k = 0; k < 8; ++k) {
            int id = __shfl_sync(0xffffffffu, e1, h * 8 + k);
            v[k] = __ldg(&emb[(size_t)id * DIMV + lane]);
        }
        #pragma unroll
        for (int k = 0; k < 8; ++k)
            x0 += __shfl_sync(0xffffffffu, a0, h * 8 + k) * v[k];
    }
    float y0 = bl;
    #pragma unroll
    for (int j = 0; j < DIMV; ++j)
        y0 += __shfl_sync(0xffffffffu, x0, j) * Wcol[j];
    float xf = sigm(y0);

    // final aggregate over t1 rows (coalesced) + matvec + score
    const float* tb = g_t + (size_t)b * KN * DIMV;
    #pragma unroll
    for (int h = 0; h < 2; ++h) {
        float v[8];
        #pragma unroll
        for (int k = 0; k < 8; ++k)
            v[k] = __ldg(&tb[(h * 8 + k) * DIMV + lane]);
        #pragma unroll
        for (int k = 0; k < 8; ++k)
            xf += __shfl_sync(0xffffffffu, a0, h * 8 + k) * v[k];
    }
    float yf = bl;
    #pragma unroll
    for (int j = 0; j < DIMV; ++j)
        yf += __shfl_sync(0xffffffffu, xf, j) * Wcol[j];
    float f = tanhf(yf);

    float s = __ldg(&g_uemb[b * DIMV + lane]) * f;
    #pragma unroll
    for (int o = 16; o > 0; o >>= 1) s += __shfl_xor_sync(0xffffffffu, s, o);
    if (lane == 0) out[b] = sigm(s);
}

extern "C" void kernel_launch(void* const* d_in, const int* in_sizes, int n_in,
                              void* d_out, int out_size) {
    const int*   users        = (const int*)  d_in[0];
    const int*   items        = (const int*)  d_in[1];
    const float* entity_emb   = (const float*)d_in[2];
    const float* relation_emb = (const float*)d_in[3];
    const int*   adj_entity   = (const int*)  d_in[4];
    const int*   adj_relation = (const int*)  d_in[5];
    const int*   user_history = (const int*)  d_in[6];
    const float* W            = (const float*)d_in[7];
    const float* b            = (const float*)d_in[8];
    float* out = (float*)d_out;

    int B = in_sizes[0];
    ka_kernel<<<(B + 7) / 8, 256>>>(users, items, entity_emb, relation_emb,
                                    adj_entity, adj_relation, user_history, B);
    kb_kernel<<<(B * 4 + 7) / 8, 256>>>(entity_emb, W, b, B);
    kc_kernel<<<(B + 7) / 8, 256>>>(items, entity_emb, W, b, out, B);
}

// round 12
// speedup vs baseline: 1.3616x; 1.0438x over previous
#include <cuda_runtime.h>
#include <math.h>

#define DIMV 32
#define KN 16
#define NREL 60
#define MAXB 8192

// scratch (device globals)
__device__ float g_uemb [MAXB * DIMV];
__device__ int   g_e1id [MAXB * KN];
__device__ float g_attn0[MAXB * KN];
__device__ int   g_e2id [MAXB * KN * KN];
__device__ float g_attn1[MAXB * KN * KN];
__device__ float g_t    [MAXB * KN * DIMV];

__device__ __forceinline__ float sigm(float x) { return 1.f / (1.f + __expf(-x)); }

__device__ __forceinline__ float softmax16(float sc) {
    float m = sc;
    #pragma unroll
    for (int o = 8; o > 0; o >>= 1) m = fmaxf(m, __shfl_xor_sync(0xffffffffu, m, o, 16));
    float e = __expf(sc - m);
    float s = e;
    #pragma unroll
    for (int o = 8; o > 0; o >>= 1) s += __shfl_xor_sync(0xffffffffu, s, o, 16);
    return e / s;
}

__device__ __forceinline__ float udr_lookup(float u0, float u1, int rid) {
    float a = __shfl_sync(0xffffffffu, u0, rid & 31);
    float b = __shfl_sync(0xffffffffu, u1, rid & 31);
    return (rid < 32) ? a : b;
}

// ---- KA: warp per element; forced 32-reg compile. ------------------------
__global__ __launch_bounds__(256, 8) void ka_kernel(
    const int*   __restrict__ users,
    const int*   __restrict__ items,
    const float* __restrict__ emb,
    const float* __restrict__ rel,
    const int*   __restrict__ adjE,
    const int*   __restrict__ adjR,
    const int*   __restrict__ hist,
    int B)
{
    __shared__ float rels[NREL * DIMV];   // swizzled [r*32 + ((d+r)&31)]

    const int tid = threadIdx.x, lane = tid & 31, w = tid >> 5;
    #pragma unroll
    for (int i = tid; i < NREL * DIMV; i += 256) {
        int r = i >> 5, d = i & 31;
        rels[r * DIMV + ((d + r) & 31)] = __ldg(&rel[i]);
    }
    __syncthreads();

    const int b = blockIdx.x * 8 + w;
    if (b >= B) return;

    const int uid  = __ldg(&users[b]);
    const int item = __ldg(&items[b]);
    const int kl   = lane & 15;

    const int hid = __ldg(&hist[(size_t)uid  * KN + kl]);
    const int e1  = __ldg(&adjE[(size_t)item * KN + kl]);
    const int r0  = __ldg(&adjR[(size_t)item * KN + kl]);

    // user embedding: batch the 16 independent row loads
    float hv[8];
    float us = 0.f;
    #pragma unroll
    for (int h = 0; h < 2; ++h) {
        #pragma unroll
        for (int k = 0; k < 8; ++k) {
            int id = __shfl_sync(0xffffffffu, hid, h * 8 + k);
            hv[k] = __ldg(&emb[(size_t)id * DIMV + lane]);
        }
        #pragma unroll
        for (int k = 0; k < 8; ++k) us += hv[k];
    }
    const float uemb = us * (1.f / 16.f);
    g_uemb[b * DIMV + lane] = uemb;

    // udotr: lane r holds udotr[r] (u0) and udotr[r+32] (u1)
    float u0 = 0.f, u1 = 0.f;
    const int r2 = lane + 32;
    #pragma unroll
    for (int d = 0; d < DIMV; ++d) {
        float ud = __shfl_sync(0xffffffffu, uemb, d);
        u0 += ud * rels[lane * DIMV + ((d + lane) & 31)];
        if (r2 < NREL) u1 += ud * rels[r2 * DIMV + ((d + r2) & 31)];
    }

    // hop-0 attention + e1 ids
    float a0 = softmax16(udr_lookup(u0, u1, r0));
    if (lane < KN) {
        g_e1id [b * KN + lane] = e1;
        g_attn0[b * KN + lane] = a0;
    }

    // hop-2 adjacency + hop-1 attention: 8 iters x (2 rows x 16 cols)
    #pragma unroll
    for (int p = 0; p < 8; ++p) {
        int row  = 2 * p + (lane >> 4);
        int base = __shfl_sync(0xffffffffu, e1, row);
        int id   = __ldg(&adjE[(size_t)base * KN + kl]);
        int rid  = __ldg(&adjR[(size_t)base * KN + kl]);
        float a  = softmax16(udr_lookup(u0, u1, rid));
        size_t o = (size_t)b * 256 + row * KN + kl;
        g_e2id [o] = id;
        g_attn1[o] = a;
    }
}

// ---- KB: warp per quad. Shared W, pipelined gather, high occupancy. ------
__global__ __launch_bounds__(256, 6) void kb_kernel(
    const float* __restrict__ emb,
    const float* __restrict__ W,
    const float* __restrict__ bvec,
    int B)
{
    __shared__ float Ws[DIMV * DIMV];
    __shared__ float bs[DIMV];

    const int tid = threadIdx.x, lane = tid & 31, w = tid >> 5;
    #pragma unroll
    for (int i = tid; i < DIMV * DIMV; i += 256) Ws[i] = __ldg(&W[i]);
    if (tid < DIMV) bs[tid] = __ldg(&bvec[tid]);
    __syncthreads();

    const int q = blockIdx.x * 8 + w;
    const int b = q >> 2, quad = q & 3;
    if (b >= B) return;

    // 64 ids + 64 weights for this quad, 2 per lane (coalesced)
    const int2*   idp = (const int2*)  (g_e2id  + (size_t)b * 256 + quad * 64);
    const float2* wtp = (const float2*)(g_attn1 + (size_t)b * 256 + quad * 64);
    const int2   id2 = __ldg(&idp[lane]);
    const float2 wt2 = __ldg(&wtp[lane]);

    // all 4 self rows issued up front (independent)
    const int s4 = (lane < 4) ? __ldg(&g_e1id[b * KN + quad * 4 + lane]) : 0;
    float selfv[4];
    #pragma unroll
    for (int t = 0; t < 4; ++t) {
        int sid = __shfl_sync(0xffffffffu, s4, t);
        selfv[t] = __ldg(&emb[(size_t)sid * DIMV + lane]);
    }

    // software-pipelined gather: issue batch for next half while reducing
    // current. halves: (t,h) for t in 0..3, h in 0..1; 8 rows per half.
    float va[4], vb[4];      // current in-flight half
    float na[4], nb[4];      // next half
    #pragma unroll
    for (int p = 0; p < 4; ++p) {
        int src = 0 * 8 + 0 * 4 + p;
        int ia = __shfl_sync(0xffffffffu, id2.x, src);
        int ib = __shfl_sync(0xffffffffu, id2.y, src);
        va[p] = __ldg(&emb[(size_t)ia * DIMV + lane]);
        vb[p] = __ldg(&emb[(size_t)ib * DIMV + lane]);
    }

    float x = 0.f;
    #pragma unroll
    for (int t = 0; t < 4; ++t) {
        if (t > 0) x = selfv[t - 1];
        else       x = selfv[0];
        float xacc = selfv[t];
        #pragma unroll
        for (int h = 0; h < 2; ++h) {
            // issue next half's loads (if any) before reducing this half
            const int nt = (h == 1) ? t + 1 : t;
            const int nh = (h == 1) ? 0 : 1;
            if (nt < 4) {
                #pragma unroll
                for (int p = 0; p < 4; ++p) {
                    int src = nt * 8 + nh * 4 + p;
                    int ia = __shfl_sync(0xffffffffu, id2.x, src);
                    int ib = __shfl_sync(0xffffffffu, id2.y, src);
                    na[p] = __ldg(&emb[(size_t)ia * DIMV + lane]);
                    nb[p] = __ldg(&emb[(size_t)ib * DIMV + lane]);
                }
            }
            // reduce current half
            #pragma unroll
            for (int p = 0; p < 4; ++p) {
                int src = t * 8 + h * 4 + p;
                xacc += __shfl_sync(0xffffffffu, wt2.x, src) * va[p];
                xacc += __shfl_sync(0xffffffffu, wt2.y, src) * vb[p];
            }
            // rotate buffers
            #pragma unroll
            for (int p = 0; p < 4; ++p) { va[p] = na[p]; vb[p] = nb[p]; }
        }

        float y = bs[lane];
        #pragma unroll
        for (int j = 0; j < DIMV; ++j)
            y += __shfl_sync(0xffffffffu, xacc, j) * Ws[j * DIMV + lane];

        g_t[((size_t)b * KN + quad * 4 + t) * DIMV + lane] = sigm(y);
    }
}

// ---- KC: warp per element. hop-0 node + final matvec + score. ------------
__global__ __launch_bounds__(256, 4) void kc_kernel(
    const int*   __restrict__ items,
    const float* __restrict__ emb,
    const float* __restrict__ W,
    const float* __restrict__ bvec,
    float*       __restrict__ out,
    int B)
{
    const int tid = threadIdx.x, lane = tid & 31, w = tid >> 5;
    const int b = blockIdx.x * 8 + w;
    if (b >= B) return;

    float Wcol[DIMV];
    #pragma unroll
    for (int j = 0; j < DIMV; ++j) Wcol[j] = __ldg(&W[j * DIMV + lane]);
    const float bl = __ldg(&bvec[lane]);

    const float a0 = (lane < KN) ? __ldg(&g_attn0[b * KN + lane]) : 0.f;
    const int   e1 = (lane < KN) ? __ldg(&g_e1id [b * KN + lane]) : 0;
    const int item = __ldg(&items[b]);

    // hop-0 node: item row + 16 e1-row gather
    float x0 = __ldg(&emb[(size_t)item * DIMV + lane]);
    #pragma unroll
    for (int h = 0; h < 2; ++h) {
        float v[8];
        #pragma unroll
        for (int k = 0; k < 8; ++k) {
            int id = __shfl_sync(0xffffffffu, e1, h * 8 + k);
            v[k] = __ldg(&emb[(size_t)id * DIMV + lane]);
        }
        #pragma unroll
        for (int k = 0; k < 8; ++k)
            x0 += __shfl_sync(0xffffffffu, a0, h * 8 + k) * v[k];
    }
    float y0 = bl;
    #pragma unroll
    for (int j = 0; j < DIMV; ++j)
        y0 += __shfl_sync(0xffffffffu, x0, j) * Wcol[j];
    float xf = sigm(y0);

    // final aggregate over t1 rows (coalesced) + matvec + score
    const float* tb = g_t + (size_t)b * KN * DIMV;
    #pragma unroll
    for (int h = 0; h < 2; ++h) {
        float v[8];
        #pragma unroll
        for (int k = 0; k < 8; ++k)
            v[k] = __ldg(&tb[(h * 8 + k) * DIMV + lane]);
        #pragma unroll
        for (int k = 0; k < 8; ++k)
            xf += __shfl_sync(0xffffffffu, a0, h * 8 + k) * v[k];
    }
    float yf = bl;
    #pragma unroll
    for (int j = 0; j < DIMV; ++j)
        yf += __shfl_sync(0xffffffffu, xf, j) * Wcol[j];
    float f = tanhf(yf);

    float s = __ldg(&g_uemb[b * DIMV + lane]) * f;
    #pragma unroll
    for (int o = 16; o > 0; o >>= 1) s += __shfl_xor_sync(0xffffffffu, s, o);
    if (lane == 0) out[b] = sigm(s);
}

extern "C" void kernel_launch(void* const* d_in, const int* in_sizes, int n_in,
                              void* d_out, int out_size) {
    const int*   users        = (const int*)  d_in[0];
    const int*   items        = (const int*)  d_in[1];
    const float* entity_emb   = (const float*)d_in[2];
    const float* relation_emb = (const float*)d_in[3];
    const int*   adj_entity   = (const int*)  d_in[4];
    const int*   adj_relation = (const int*)  d_in[5];
    const int*   user_history = (const int*)  d_in[6];
    const float* W            = (const float*)d_in[7];
    const float* b            = (const float*)d_in[8];
    float* out = (float*)d_out;

    int B = in_sizes[0];
    ka_kernel<<<(B + 7) / 8, 256>>>(users, items, entity_emb, relation_emb,
                                    adj_entity, adj_relation, user_history, B);
    kb_kernel<<<(B * 4 + 7) / 8, 256>>>(entity_emb, W, b, B);
    kc_kernel<<<(B + 7) / 8, 256>>>(items, entity_emb, W, b, out, B);
}